// round 15
// baseline (speedup 1.0000x reference)
#include <cuda_runtime.h>
#include <cuda_fp16.h>
#include <cuda_bf16.h>
#include <mma.h>
#include <cstdint>

#define N_NODES 40000
#define N_EDGES 640000
#define DIN 128
#define DOUT 64

#define GEMM_BLOCKS (N_NODES / 64)                   // 625
#define RP_BLOCKS   ((N_EDGES + 1 + 255) / 256)      // 2502

// fp16 intermediates (row = 64 halves = 128 B = 8 uint4)
__device__ __half g_t0[N_NODES * DOUT];
__device__ __half g_t1[N_NODES * DOUT];
__device__ float  g_Wc[DIN * DOUT];
__device__ int    g_row_ptr[N_NODES + 1];

// Wc = (W1 @ W2) @ W3 in one kernel.
__global__ void __launch_bounds__(128)
wc_kernel(const float* __restrict__ W1, const float* __restrict__ W2,
          const float* __restrict__ W3) {
    __shared__ float sW2[DIN * DIN];
    __shared__ float row[DIN];
    __shared__ float t1[DIN];

    const int i = blockIdx.x, j = threadIdx.x;

    const float4* W24 = (const float4*)W2;
    float4* sW24 = (float4*)sW2;
    #pragma unroll
    for (int it = 0; it < 32; ++it)
        sW24[j + it * 128] = W24[j + it * 128];
    row[j] = W1[i * DIN + j];
    __syncthreads();

    float acc = 0.f;
    #pragma unroll 8
    for (int k = 0; k < DIN; ++k) acc += row[k] * sW2[k * DIN + j];
    t1[j] = acc;
    __syncthreads();

    if (j < DOUT) {
        float acc2 = 0.f;
        #pragma unroll 8
        for (int k = 0; k < DIN; ++k) acc2 += t1[k] * __ldg(&W3[k * DOUT + j]);
        g_Wc[i * DOUT + j] = acc2;
    }
}

// Fused: GEMM blocks compute t0 = F @ Wc via HMMA; trailing blocks build row_ptr.
__global__ void __launch_bounds__(256)
gemm_rp_kernel(const float* __restrict__ F, __half* __restrict__ out,
               const int* __restrict__ dst) {
    using namespace nvcuda::wmma;

    if (blockIdx.x >= GEMM_BLOCKS) {
        int e = (blockIdx.x - GEMM_BLOCKS) * 256 + threadIdx.x;
        if (e <= N_EDGES) {
            int d_prev = (e == 0) ? -1 : __ldg(&dst[e - 1]);
            int d_cur  = (e == N_EDGES) ? N_NODES : __ldg(&dst[e]);
            for (int k = d_prev + 1; k <= d_cur; ++k)
                g_row_ptr[k] = e;
        }
        return;
    }

    __shared__ __half sF[64 * DIN];
    __shared__ __half sW[DIN * DOUT];
    __shared__ float  sO[64 * DOUT];

    const int tid = threadIdx.x;
    const int n0 = blockIdx.x * 64;

    const float4* F4 = (const float4*)(F + (size_t)n0 * DIN);
    const float4* W4 = (const float4*)g_Wc;
    float4 fr[8], wr[8];
    #pragma unroll
    for (int i = 0; i < 8; ++i) fr[i] = F4[tid + i * 256];
    #pragma unroll
    for (int i = 0; i < 8; ++i) wr[i] = W4[tid + i * 256];

    __half2* sF2 = (__half2*)sF;
    __half2* sW2 = (__half2*)sW;
    #pragma unroll
    for (int i = 0; i < 8; ++i) {
        const int p = tid + i * 256;
        sF2[2 * p]     = __floats2half2_rn(fr[i].x, fr[i].y);
        sF2[2 * p + 1] = __floats2half2_rn(fr[i].z, fr[i].w);
        sW2[2 * p]     = __floats2half2_rn(wr[i].x, wr[i].y);
        sW2[2 * p + 1] = __floats2half2_rn(wr[i].z, wr[i].w);
    }
    __syncthreads();

    const int w = tid >> 5;
    const int mt = w >> 1;
    const int nb = (w & 1) * 2;

    fragment<accumulator, 16, 16, 16, float> acc0, acc1;
    fill_fragment(acc0, 0.f);
    fill_fragment(acc1, 0.f);

    #pragma unroll
    for (int kt = 0; kt < DIN / 16; ++kt) {
        fragment<matrix_a, 16, 16, 16, __half, row_major> a;
        load_matrix_sync(a, &sF[(mt * 16) * DIN + kt * 16], DIN);
        fragment<matrix_b, 16, 16, 16, __half, row_major> b0, b1;
        load_matrix_sync(b0, &sW[(kt * 16) * DOUT + nb * 16], DOUT);
        load_matrix_sync(b1, &sW[(kt * 16) * DOUT + (nb + 1) * 16], DOUT);
        mma_sync(acc0, a, b0, acc0);
        mma_sync(acc1, a, b1, acc1);
    }

    __syncthreads();
    store_matrix_sync(&sO[(mt * 16) * DOUT + nb * 16], acc0, DOUT, mem_row_major);
    store_matrix_sync(&sO[(mt * 16) * DOUT + (nb + 1) * 16], acc1, DOUT, mem_row_major);
    __syncthreads();

    const float4* sO4 = (const float4*)sO;
    uint2* out2 = (uint2*)(out + (size_t)n0 * DOUT);
    #pragma unroll
    for (int i = 0; i < 4; ++i) {
        const int p = tid + i * 256;
        float4 v = sO4[p];
        __half2 h0 = __floats2half2_rn(v.x, v.y);
        __half2 h1 = __floats2half2_rn(v.z, v.w);
        uint2 o;
        o.x = *reinterpret_cast<unsigned*>(&h0);
        o.y = *reinterpret_cast<unsigned*>(&h1);
        out2[p] = o;
    }
}

// --- fp16 helpers ---
__device__ __forceinline__ __half2 u2h(unsigned v) { return *reinterpret_cast<__half2*>(&v); }
__device__ __forceinline__ unsigned h2u(__half2 v) { return *reinterpret_cast<unsigned*>(&v); }

__device__ __forceinline__ uint4 hmerge(uint4 x, uint4 y) {
    uint4 r;
    r.x = h2u(__hadd2(u2h(x.x), u2h(y.x)));
    r.y = h2u(__hadd2(u2h(x.y), u2h(y.y)));
    r.z = h2u(__hadd2(u2h(x.z), u2h(y.z)));
    r.w = h2u(__hadd2(u2h(x.w), u2h(y.w)));
    return r;
}

__device__ __forceinline__ void hacc(float* a, uint4 v) {
    float2 f;
    f = __half22float2(u2h(v.x)); a[0] += f.x; a[1] += f.y;
    f = __half22float2(u2h(v.y)); a[2] += f.x; a[3] += f.y;
    f = __half22float2(u2h(v.z)); a[4] += f.x; a[5] += f.y;
    f = __half22float2(u2h(v.w)); a[6] += f.x; a[7] += f.y;
}

// Aggregation hop, fp16 rows (128 B = 8 uint4), fp32 accumulation.
// R14 shape widened: 512-thread blocks = 16 nodes, GCHUNK=512 so the average
// block (256 edges) stages in ONE chunk — half the barriers per edge.
// s_idx holds byte offsets; lane base pre-offset by oct*16 (single-IADD addr).
#define GCHUNK 512
template <int OUT_HALF>
__global__ void __launch_bounds__(512)
gather_h_kernel(const int* __restrict__ src,
                const __half* __restrict__ h_in,
                void* __restrict__ h_out) {
    __shared__ int s_idx[GCHUNK];

    const int tid  = threadIdx.x;
    const int wid  = tid >> 5;     // 0..15
    const int lane = tid & 31;
    const int oct  = lane & 7;
    const int slot = lane >> 3;

    const int n0 = blockIdx.x * 16;
    const int n  = n0 + wid;

    const int blk_beg = g_row_ptr[n0];
    const int blk_end = g_row_ptr[n0 + 16];
    const int beg = g_row_ptr[n];
    const int end = g_row_ptr[n + 1];

    const char* in_base = (const char*)h_in + oct * 16;

    float a[8] = {};

    for (int base = blk_beg; base < blk_end; base += GCHUNK) {
        if (base + tid < blk_end)
            s_idx[tid] = __ldg(&src[base + tid]) << 7;   // byte offset of row
        __syncthreads();

        const int hi = min(end, base + GCHUNK);
        int off = max(beg, base) - base;
        int r = hi - (base + off);

        // main: 16 edges per warp-iter, 4 independent LDG.128 per lane
        while (r >= 16) {
            uint4 v0 = *(const uint4*)(in_base + s_idx[off + slot     ]);
            uint4 v1 = *(const uint4*)(in_base + s_idx[off + slot +  4]);
            uint4 v2 = *(const uint4*)(in_base + s_idx[off + slot +  8]);
            uint4 v3 = *(const uint4*)(in_base + s_idx[off + slot + 12]);
            hacc(a, hmerge(v0, v1));
            hacc(a, hmerge(v2, v3));
            off += 16; r -= 16;
        }
        // epilogue: remainder 0..15 in ONE window, 4 predicated independent loads
        {
            uint4 v0 = make_uint4(0u,0u,0u,0u), v1 = v0, v2 = v0, v3 = v0;
            if (slot      < r) v0 = *(const uint4*)(in_base + s_idx[off + slot     ]);
            if (slot +  4 < r) v1 = *(const uint4*)(in_base + s_idx[off + slot +  4]);
            if (slot +  8 < r) v2 = *(const uint4*)(in_base + s_idx[off + slot +  8]);
            if (slot + 12 < r) v3 = *(const uint4*)(in_base + s_idx[off + slot + 12]);
            hacc(a, hmerge(v0, v1));   // zero halves add 0.0f exactly
            hacc(a, hmerge(v2, v3));
        }
        __syncthreads();
    }

    #pragma unroll
    for (int k = 0; k < 8; ++k) {
        a[k] += __shfl_down_sync(0xffffffffu, a[k], 16);
        a[k] += __shfl_down_sync(0xffffffffu, a[k], 8);
    }

    if (slot == 0) {
        if (OUT_HALF) {
            uint4 o;
            o.x = h2u(__floats2half2_rn(a[0], a[1]));
            o.y = h2u(__floats2half2_rn(a[2], a[3]));
            o.z = h2u(__floats2half2_rn(a[4], a[5]));
            o.w = h2u(__floats2half2_rn(a[6], a[7]));
            ((uint4*)h_out)[(size_t)n * 8 + oct] = o;
        } else {
            float4* out4 = (float4*)h_out;
            out4[(size_t)n * 16 + oct * 2]     = make_float4(a[0], a[1], a[2], a[3]);
            out4[(size_t)n * 16 + oct * 2 + 1] = make_float4(a[4], a[5], a[6], a[7]);
        }
    }
}

extern "C" void kernel_launch(void* const* d_in, const int* in_sizes, int n_in,
                              void* d_out, int out_size) {
    const int*   src      = (const int*)d_in[0];
    const int*   dst      = (const int*)d_in[1];
    const float* features = (const float*)d_in[2];
    const float* W1       = (const float*)d_in[3];
    const float* W2       = (const float*)d_in[4];
    const float* W3       = (const float*)d_in[5];

    __half* t0; __half* t1;
    cudaGetSymbolAddress((void**)&t0, g_t0);
    cudaGetSymbolAddress((void**)&t1, g_t1);

    wc_kernel<<<DIN, DIN>>>(W1, W2, W3);

    gemm_rp_kernel<<<GEMM_BLOCKS + RP_BLOCKS, 256>>>(features, t0, dst);

    const int gblocks = N_NODES / 16;   // 2500
    gather_h_kernel<1><<<gblocks, 512>>>(src, t0, t1);
    gather_h_kernel<1><<<gblocks, 512>>>(src, t1, t0);
    gather_h_kernel<0><<<gblocks, 512>>>(src, t0, d_out);
}

// round 16
// speedup vs baseline: 1.0917x; 1.0917x over previous
#include <cuda_runtime.h>
#include <cuda_fp16.h>
#include <cuda_bf16.h>
#include <mma.h>
#include <cstdint>

#define N_NODES 40000
#define N_EDGES 640000
#define DIN 128
#define DOUT 64

#define GEMM_BLOCKS (N_NODES / 64)                   // 625
#define RP_BLOCKS   ((N_EDGES + 1 + 255) / 256)      // 2502

// fp16 intermediates (row = 64 halves = 128 B)
__device__ __half g_t0[N_NODES * DOUT];
__device__ __half g_t1[N_NODES * DOUT];
__device__ float  g_Wc[DIN * DOUT];
__device__ int    g_row_ptr[N_NODES + 1];

// Wc = (W1 @ W2) @ W3 in one kernel.
__global__ void __launch_bounds__(128)
wc_kernel(const float* __restrict__ W1, const float* __restrict__ W2,
          const float* __restrict__ W3) {
    __shared__ float sW2[DIN * DIN];
    __shared__ float row[DIN];
    __shared__ float t1[DIN];

    const int i = blockIdx.x, j = threadIdx.x;

    const float4* W24 = (const float4*)W2;
    float4* sW24 = (float4*)sW2;
    #pragma unroll
    for (int it = 0; it < 32; ++it)
        sW24[j + it * 128] = W24[j + it * 128];
    row[j] = W1[i * DIN + j];
    __syncthreads();

    float acc = 0.f;
    #pragma unroll 8
    for (int k = 0; k < DIN; ++k) acc += row[k] * sW2[k * DIN + j];
    t1[j] = acc;
    __syncthreads();

    if (j < DOUT) {
        float acc2 = 0.f;
        #pragma unroll 8
        for (int k = 0; k < DIN; ++k) acc2 += t1[k] * __ldg(&W3[k * DOUT + j]);
        g_Wc[i * DOUT + j] = acc2;
    }
}

// Fused: GEMM blocks compute t0 = F @ Wc via HMMA; trailing blocks build row_ptr.
__global__ void __launch_bounds__(256)
gemm_rp_kernel(const float* __restrict__ F, __half* __restrict__ out,
               const int* __restrict__ dst) {
    using namespace nvcuda::wmma;

    if (blockIdx.x >= GEMM_BLOCKS) {
        int e = (blockIdx.x - GEMM_BLOCKS) * 256 + threadIdx.x;
        if (e <= N_EDGES) {
            int d_prev = (e == 0) ? -1 : __ldg(&dst[e - 1]);
            int d_cur  = (e == N_EDGES) ? N_NODES : __ldg(&dst[e]);
            for (int k = d_prev + 1; k <= d_cur; ++k)
                g_row_ptr[k] = e;
        }
        return;
    }

    __shared__ __half sF[64 * DIN];
    __shared__ __half sW[DIN * DOUT];
    __shared__ float  sO[64 * DOUT];

    const int tid = threadIdx.x;
    const int n0 = blockIdx.x * 64;

    const float4* F4 = (const float4*)(F + (size_t)n0 * DIN);
    const float4* W4 = (const float4*)g_Wc;
    float4 fr[8], wr[8];
    #pragma unroll
    for (int i = 0; i < 8; ++i) fr[i] = F4[tid + i * 256];
    #pragma unroll
    for (int i = 0; i < 8; ++i) wr[i] = W4[tid + i * 256];

    __half2* sF2 = (__half2*)sF;
    __half2* sW2 = (__half2*)sW;
    #pragma unroll
    for (int i = 0; i < 8; ++i) {
        const int p = tid + i * 256;
        sF2[2 * p]     = __floats2half2_rn(fr[i].x, fr[i].y);
        sF2[2 * p + 1] = __floats2half2_rn(fr[i].z, fr[i].w);
        sW2[2 * p]     = __floats2half2_rn(wr[i].x, wr[i].y);
        sW2[2 * p + 1] = __floats2half2_rn(wr[i].z, wr[i].w);
    }
    __syncthreads();

    const int w = tid >> 5;
    const int mt = w >> 1;
    const int nb = (w & 1) * 2;

    fragment<accumulator, 16, 16, 16, float> acc0, acc1;
    fill_fragment(acc0, 0.f);
    fill_fragment(acc1, 0.f);

    #pragma unroll
    for (int kt = 0; kt < DIN / 16; ++kt) {
        fragment<matrix_a, 16, 16, 16, __half, row_major> a;
        load_matrix_sync(a, &sF[(mt * 16) * DIN + kt * 16], DIN);
        fragment<matrix_b, 16, 16, 16, __half, row_major> b0, b1;
        load_matrix_sync(b0, &sW[(kt * 16) * DOUT + nb * 16], DOUT);
        load_matrix_sync(b1, &sW[(kt * 16) * DOUT + (nb + 1) * 16], DOUT);
        mma_sync(acc0, a, b0, acc0);
        mma_sync(acc1, a, b1, acc1);
    }

    __syncthreads();
    store_matrix_sync(&sO[(mt * 16) * DOUT + nb * 16], acc0, DOUT, mem_row_major);
    store_matrix_sync(&sO[(mt * 16) * DOUT + (nb + 1) * 16], acc1, DOUT, mem_row_major);
    __syncthreads();

    const float4* sO4 = (const float4*)sO;
    uint2* out2 = (uint2*)(out + (size_t)n0 * DOUT);
    #pragma unroll
    for (int i = 0; i < 4; ++i) {
        const int p = tid + i * 256;
        float4 v = sO4[p];
        __half2 h0 = __floats2half2_rn(v.x, v.y);
        __half2 h1 = __floats2half2_rn(v.z, v.w);
        uint2 o;
        o.x = *reinterpret_cast<unsigned*>(&h0);
        o.y = *reinterpret_cast<unsigned*>(&h1);
        out2[p] = o;
    }
}

// --- fp16 helpers ---
__device__ __forceinline__ __half2 u2h(unsigned v) { return *reinterpret_cast<__half2*>(&v); }
__device__ __forceinline__ unsigned h2u(__half2 v) { return *reinterpret_cast<unsigned*>(&v); }

// Aggregation hop, fp16 rows (128 B), fp32 accumulation.
// LANE = COLUMN-PAIR mapping: 32 lanes cover the whole 64-half row, so each
// edge is ONE coalesced LDG.32 warp-instr (1 L2 line), s_idx reads broadcast,
// each lane owns 2 outputs end-to-end — NO cross-lane reduction, 1-instr store.
// Main window: 8 independent edges; depth-1 fp16 pair merge (same arithmetic
// as R12/R14). Block = 8 warps = 8 nodes, smem staging as in R14.
#define GCHUNK 256
template <int OUT_HALF>
__global__ void __launch_bounds__(256)
gather_h_kernel(const int* __restrict__ src,
                const __half* __restrict__ h_in,
                void* __restrict__ h_out) {
    __shared__ int s_idx[GCHUNK];

    const int tid  = threadIdx.x;
    const int wid  = tid >> 5;
    const int lane = tid & 31;

    const int n0 = blockIdx.x * 8;
    const int n  = n0 + wid;

    const int blk_beg = g_row_ptr[n0];
    const int blk_end = g_row_ptr[n0 + 8];
    const int beg = g_row_ptr[n];
    const int end = g_row_ptr[n + 1];

    const char* in_base = (const char*)h_in + lane * 4;   // lane's uint within row

    float ax = 0.f, ay = 0.f;

    for (int base = blk_beg; base < blk_end; base += GCHUNK) {
        if (base + tid < blk_end)
            s_idx[tid] = __ldg(&src[base + tid]) << 7;   // byte offset of row
        __syncthreads();

        const int hi = min(end, base + GCHUNK);
        int off = max(beg, base) - base;
        int r = hi - (base + off);

        // main: 8 edges per iter, 8 independent LDG.32 per lane (broadcast idx)
        while (r >= 8) {
            unsigned v0 = *(const unsigned*)(in_base + s_idx[off + 0]);
            unsigned v1 = *(const unsigned*)(in_base + s_idx[off + 1]);
            unsigned v2 = *(const unsigned*)(in_base + s_idx[off + 2]);
            unsigned v3 = *(const unsigned*)(in_base + s_idx[off + 3]);
            unsigned v4 = *(const unsigned*)(in_base + s_idx[off + 4]);
            unsigned v5 = *(const unsigned*)(in_base + s_idx[off + 5]);
            unsigned v6 = *(const unsigned*)(in_base + s_idx[off + 6]);
            unsigned v7 = *(const unsigned*)(in_base + s_idx[off + 7]);
            __half2 m0 = __hadd2(u2h(v0), u2h(v1));
            __half2 m1 = __hadd2(u2h(v2), u2h(v3));
            __half2 m2 = __hadd2(u2h(v4), u2h(v5));
            __half2 m3 = __hadd2(u2h(v6), u2h(v7));
            float2 f0 = __half22float2(m0); ax += f0.x; ay += f0.y;
            float2 f1 = __half22float2(m1); ax += f1.x; ay += f1.y;
            float2 f2 = __half22float2(m2); ax += f2.x; ay += f2.y;
            float2 f3 = __half22float2(m3); ax += f3.x; ay += f3.y;
            off += 8; r -= 8;
        }
        // epilogue: remainder 0..7 in ONE window, predicated independent loads
        {
            unsigned v0 = 0u, v1 = 0u, v2 = 0u, v3 = 0u;
            unsigned v4 = 0u, v5 = 0u, v6 = 0u, v7 = 0u;
            if (0 < r) v0 = *(const unsigned*)(in_base + s_idx[off + 0]);
            if (1 < r) v1 = *(const unsigned*)(in_base + s_idx[off + 1]);
            if (2 < r) v2 = *(const unsigned*)(in_base + s_idx[off + 2]);
            if (3 < r) v3 = *(const unsigned*)(in_base + s_idx[off + 3]);
            if (4 < r) v4 = *(const unsigned*)(in_base + s_idx[off + 4]);
            if (5 < r) v5 = *(const unsigned*)(in_base + s_idx[off + 5]);
            if (6 < r) v6 = *(const unsigned*)(in_base + s_idx[off + 6]);
            if (7 < r) v7 = *(const unsigned*)(in_base + s_idx[off + 7]);
            __half2 m0 = __hadd2(u2h(v0), u2h(v1));   // zero halves add exactly
            __half2 m1 = __hadd2(u2h(v2), u2h(v3));
            __half2 m2 = __hadd2(u2h(v4), u2h(v5));
            __half2 m3 = __hadd2(u2h(v6), u2h(v7));
            float2 f0 = __half22float2(m0); ax += f0.x; ay += f0.y;
            float2 f1 = __half22float2(m1); ax += f1.x; ay += f1.y;
            float2 f2 = __half22float2(m2); ax += f2.x; ay += f2.y;
            float2 f3 = __half22float2(m3); ax += f3.x; ay += f3.y;
        }
        __syncthreads();
    }

    if (OUT_HALF) {
        ((unsigned*)h_out)[n * 32 + lane] = h2u(__floats2half2_rn(ax, ay));
    } else {
        ((float2*)h_out)[(size_t)n * 32 + lane] = make_float2(ax, ay);
    }
}

extern "C" void kernel_launch(void* const* d_in, const int* in_sizes, int n_in,
                              void* d_out, int out_size) {
    const int*   src      = (const int*)d_in[0];
    const int*   dst      = (const int*)d_in[1];
    const float* features = (const float*)d_in[2];
    const float* W1       = (const float*)d_in[3];
    const float* W2       = (const float*)d_in[4];
    const float* W3       = (const float*)d_in[5];

    __half* t0; __half* t1;
    cudaGetSymbolAddress((void**)&t0, g_t0);
    cudaGetSymbolAddress((void**)&t1, g_t1);

    wc_kernel<<<DIN, DIN>>>(W1, W2, W3);

    gemm_rp_kernel<<<GEMM_BLOCKS + RP_BLOCKS, 256>>>(features, t0, dst);

    const int gblocks = N_NODES / 8;   // 5000
    gather_h_kernel<1><<<gblocks, 256>>>(src, t0, t1);
    gather_h_kernel<1><<<gblocks, 256>>>(src, t1, t0);
    gather_h_kernel<0><<<gblocks, 256>>>(src, t0, d_out);
}